// round 14
// baseline (speedup 1.0000x reference)
#include <cuda_runtime.h>
#include <cstdint>

#define Bn 8
#define Hn 64
#define Wn 64
#define HW 4096
#define KK 9
#define EPSV 1e-4f
#define SA 136   // wn_s row stride (floats)
#define SB 36    // cols_s row stride (floats)

#define WN_FL   (32 * SA)
#define COL_FL  (128 * SB)
#define ST_FL   (128 * 8)
#define SMEM_BYTES ((2 * (WN_FL + COL_FL) + 2 * ST_FL) * 4)   // 79872 B

__device__ float g_xt[Bn * HW * 128];       // x transposed [b][hw][c]
__device__ float g_wnt[KK * 128 * 128];     // wn [k][c][o-permuted], tf32-rounded

__device__ __forceinline__ float to_tf32(float x) {
    float r; asm("cvt.rna.tf32.f32 %0, %1;" : "=f"(r) : "f"(x)); return r;
}
__device__ __forceinline__ uint32_t smem_u32(const void* p) {
    uint32_t a;
    asm("{ .reg .u64 t; cvta.to.shared.u64 t, %1; cvt.u32.u64 %0, t; }" : "=r"(a) : "l"(p));
    return a;
}
__device__ __forceinline__ void mma_tf32(float* d, const uint32_t* a, const uint32_t* b) {
    asm volatile(
        "mma.sync.aligned.m16n8k8.row.col.f32.tf32.tf32.f32 "
        "{%0,%1,%2,%3}, {%4,%5,%6,%7}, {%8,%9}, {%0,%1,%2,%3};"
        : "+f"(d[0]), "+f"(d[1]), "+f"(d[2]), "+f"(d[3])
        : "r"(a[0]), "r"(a[1]), "r"(a[2]), "r"(a[3]), "r"(b[0]), "r"(b[1]));
}
#define CP_ASYNC16(dst, src) \
    asm volatile("cp.async.ca.shared.global [%0], [%1], 16;" :: "r"(dst), "l"(src) : "memory")
#define CP_COMMIT()  asm volatile("cp.async.commit_group;" ::: "memory")
#define CP_WAIT0()   asm volatile("cp.async.wait_group 0;" ::: "memory")

__device__ __forceinline__ void write_state(float* stp, const float* __restrict__ offset,
                                            int b, int k, int px, int ho0) {
    const int gho = ho0 + (px >> 6), gwo = px & 63;
    const int ky = k / 3, kx = k - ky * 3;
    const float offy = __ldg(&offset[(((b * 18) + 2 * k    ) * Hn + gho) * Wn + gwo]);
    const float offx = __ldg(&offset[(((b * 18) + 2 * k + 1) * Hn + gho) * Wn + gwo]);
    const float py  = (float)(gho - 1 + ky) + offy;
    const float pxf = (float)(gwo - 1 + kx) + offx;
    const float y0f = floorf(py), x0f = floorf(pxf);
    const float ly = py - y0f, lx = pxf - x0f;
    const int y0 = (int)y0f, x0 = (int)x0f, y1 = y0 + 1, x1 = x0 + 1;
    float w00 = (1.f - ly) * (1.f - lx), w01 = (1.f - ly) * lx;
    float w10 = ly * (1.f - lx),        w11 = ly * lx;
    if (!((y0 >= 0) & (y0 < Hn) & (x0 >= 0) & (x0 < Wn))) w00 = 0.f;
    if (!((y0 >= 0) & (y0 < Hn) & (x1 >= 0) & (x1 < Wn))) w01 = 0.f;
    if (!((y1 >= 0) & (y1 < Hn) & (x0 >= 0) & (x0 < Wn))) w10 = 0.f;
    if (!((y1 >= 0) & (y1 < Hn) & (x1 >= 0) & (x1 < Wn))) w11 = 0.f;
    const int yc0 = min(max(y0, 0), Hn - 1), yc1 = min(max(y1, 0), Hn - 1);
    const int xc0 = min(max(x0, 0), Wn - 1), xc1 = min(max(x1, 0), Wn - 1);
    *(float4*)&stp[px * 8] = make_float4(w00, w01, w10, w11);
    *(float4*)&stp[px * 8 + 4] =
        make_float4(__int_as_float(yc0 * Wn + xc0), __int_as_float(yc0 * Wn + xc1),
                    __int_as_float(yc1 * Wn + xc0), __int_as_float(yc1 * Wn + xc1));
}

// ---- kernel 1: prep = transpose x (4096 blocks) + weights (36 blocks) ----
__global__ void prep_kernel(const float* __restrict__ x, const float* __restrict__ w) {
    if (blockIdx.x < 4096) {
        __shared__ float s[32][33];
        int id = blockIdx.x;
        int b = id >> 9, rest = id & 511;
        int c0 = (rest >> 7) * 32, hw0 = (rest & 127) * 32;
        int tx = threadIdx.x & 31, ty = threadIdx.x >> 5;
        #pragma unroll
        for (int p = 0; p < 4; p++)
            s[ty + p * 8][tx] = x[(size_t)(b * 128 + c0 + ty + p * 8) * HW + hw0 + tx];
        __syncthreads();
        #pragma unroll
        for (int p = 0; p < 4; p++)
            g_xt[(size_t)(b * HW + hw0 + ty + p * 8) * 128 + c0 + tx] = s[tx][ty + p * 8];
    } else {
        const int wb = blockIdx.x - 4096;
        const int k = wb >> 2, og = wb & 3;
        const int t = threadIdx.x;
        __shared__ float part[32][8];
        __shared__ float inv_s[32];
        {
            const int ol = t >> 3, sl = t & 7;
            const int o = og * 32 + ol;
            float s = 0.f;
            #pragma unroll
            for (int c = sl * 16; c < sl * 16 + 16; c++) {
                float v = w[(o * 128 + c) * KK + k]; s += v * v;
            }
            part[ol][sl] = s;
        }
        __syncthreads();
        if (t < 32) {
            float s = 0.f;
            #pragma unroll
            for (int j = 0; j < 8; j++) s += part[t][j];
            inv_s[t] = 1.0f / (sqrtf(s + 128.0f * EPSV) * 3.0f);
        }
        __syncthreads();
        #pragma unroll
        for (int r = 0; r < 16; r++) {
            int e = r * 256 + t;
            int c = e >> 5, ol = e & 31;
            int o = og * 32 + ol;
            // o-permutation: rows (g, g+8) of each 16-block adjacent (R9-verified)
            const int opos = (o >> 4) * 16 + (o & 7) * 2 + ((o >> 3) & 1);
            g_wnt[(k * 128 + c) * 128 + opos] =
                to_tf32(w[(o * 128 + c) * KK + k] * inv_s[ol]);
        }
    }
}

// ---- kernel 2: main — deferred-blend gather + tf32 mma.sync GEMM ----
__global__ __launch_bounds__(256, 2)
void deform_main_kernel(const float* __restrict__ offset, float* __restrict__ out) {
    extern __shared__ float sm[];
    float* wnb[2]  = { sm, sm + WN_FL };
    float* colb[2] = { sm + 2 * WN_FL, sm + 2 * WN_FL + COL_FL };
    float* st      = sm + 2 * WN_FL + 2 * COL_FL;
    const uint32_t wnb_u32[2] = { smem_u32(wnb[0]), smem_u32(wnb[1]) };

    const int t = threadIdx.x;
    const int b = blockIdx.x >> 5;
    const int ho0 = (blockIdx.x & 31) * 2;

    const int l8  = t & 7;
    const int pxq = t >> 3;
    const int w = t >> 5, lane = t & 31;
    const int m0 = (w & 3) * 32, n0 = (w >> 2) * 64;
    const int g = lane >> 2, q = lane & 3;
    const int mblk = (w & 3) * 2;           // 16-block base index

    float acc[2][8][4];
    #pragma unroll
    for (int mt = 0; mt < 2; mt++)
        #pragma unroll
        for (int nt = 0; nt < 8; nt++)
            #pragma unroll
            for (int r = 0; r < 4; r++) acc[mt][nt][r] = 0.f;

    const float* xb = g_xt + (size_t)b * HW * 128;

    // ---- prologue ----
    if (t < 128) write_state(st, offset, b, 0, t, ho0);
    {
        const float* src = g_wnt;
        #pragma unroll
        for (int p = 0; p < 4; p++) {
            int e16 = p * 256 + t;
            int c = e16 >> 5, off = (e16 & 31) * 4;
            CP_ASYNC16(wnb_u32[0] + (uint32_t)(c * SA + off) * 4, src + e16 * 4);
        }
        CP_COMMIT();
    }
    __syncthreads();
    #pragma unroll
    for (int p = 0; p < 4; p++) {
        const int px = p * 32 + pxq;
        float4 sw = *(const float4*)&st[px * 8];
        float4 si = *(const float4*)&st[px * 8 + 4];
        const float* base = xb + l8 * 4;
        float4 a  = *(const float4*)(base + (size_t)__float_as_int(si.x) * 128);
        float4 bb = *(const float4*)(base + (size_t)__float_as_int(si.y) * 128);
        float4 c  = *(const float4*)(base + (size_t)__float_as_int(si.z) * 128);
        float4 d  = *(const float4*)(base + (size_t)__float_as_int(si.w) * 128);
        float4 v;
        v.x = to_tf32(sw.x * a.x + sw.y * bb.x + sw.z * c.x + sw.w * d.x);
        v.y = to_tf32(sw.x * a.y + sw.y * bb.y + sw.z * c.y + sw.w * d.y);
        v.z = to_tf32(sw.x * a.z + sw.y * bb.z + sw.z * c.z + sw.w * d.z);
        v.w = to_tf32(sw.x * a.w + sw.y * bb.w + sw.z * c.w + sw.w * d.w);
        *(float4*)&colb[0][px * SB + l8 * 4] = v;
    }
    CP_WAIT0();

    // ---- pipelined main loop over 36 chunks ----
    for (int it = 0; it < 36; it++) {
        const int cur = it & 1, nxt = cur ^ 1;
        __syncthreads();

        const bool more = (it + 1 < 36);
        const float* stp = st + ((((it + 1) >> 2)) & 1) * ST_FL;
        const int ccn = (it + 1) & 3;

        float4 crA[2], crB[2], crC[2], crD[2], swr[2];
        // hoisted corner issue for sub 0 (distance: wn cp.async + state + sub0 pre-MMA)
        if (more) {
            const int px = pxq;
            swr[0] = *(const float4*)&stp[px * 8];
            float4 si = *(const float4*)&stp[px * 8 + 4];
            const float* base = xb + ccn * 32 + l8 * 4;
            crA[0] = *(const float4*)(base + (size_t)__float_as_int(si.x) * 128);
            crB[0] = *(const float4*)(base + (size_t)__float_as_int(si.y) * 128);
            crC[0] = *(const float4*)(base + (size_t)__float_as_int(si.z) * 128);
            crD[0] = *(const float4*)(base + (size_t)__float_as_int(si.w) * 128);
        }
        if (more) {
            const float* src = g_wnt + (size_t)(it + 1) * 4096;
            #pragma unroll
            for (int p = 0; p < 4; p++) {
                int e16 = p * 256 + t;
                int c = e16 >> 5, off = (e16 & 31) * 4;
                CP_ASYNC16(wnb_u32[nxt] + (uint32_t)(c * SA + off) * 4, src + e16 * 4);
            }
            CP_COMMIT();
        }
        if ((it + 2 < 36) && (((it + 2) & 3) == 0) && t < 128)
            write_state(st + (((it + 2) >> 2) & 1) * ST_FL, offset, b, (it + 2) >> 2, t, ho0);

        const float* wnc = wnb[cur];
        const float* colc = colb[cur];
        float* coln = colb[nxt];

        #pragma unroll
        for (int sub = 0; sub < 4; sub++) {
            const int sl = sub & 1, sn = sl ^ 1;
            // issue corners for sub+1 (blended one sub later)
            if (more && sub < 3) {
                const int px = (sub + 1) * 32 + pxq;
                swr[sn] = *(const float4*)&stp[px * 8];
                float4 si = *(const float4*)&stp[px * 8 + 4];
                const float* base = xb + ccn * 32 + l8 * 4;
                crA[sn] = *(const float4*)(base + (size_t)__float_as_int(si.x) * 128);
                crB[sn] = *(const float4*)(base + (size_t)__float_as_int(si.y) * 128);
                crC[sn] = *(const float4*)(base + (size_t)__float_as_int(si.z) * 128);
                crD[sn] = *(const float4*)(base + (size_t)__float_as_int(si.w) * 128);
            }
            // blend set issued one sub ago; store before this sub's MMAs
            if (more) {
                const int px = sub * 32 + pxq;
                float4 v;
                v.x = to_tf32(swr[sl].x * crA[sl].x + swr[sl].y * crB[sl].x +
                              swr[sl].z * crC[sl].x + swr[sl].w * crD[sl].x);
                v.y = to_tf32(swr[sl].x * crA[sl].y + swr[sl].y * crB[sl].y +
                              swr[sl].z * crC[sl].y + swr[sl].w * crD[sl].y);
                v.z = to_tf32(swr[sl].x * crA[sl].z + swr[sl].y * crB[sl].z +
                              swr[sl].z * crC[sl].z + swr[sl].w * crD[sl].z);
                v.w = to_tf32(swr[sl].x * crA[sl].w + swr[sl].y * crB[sl].w +
                              swr[sl].z * crC[sl].w + swr[sl].w * crD[sl].w);
                *(float4*)&coln[px * SB + l8 * 4] = v;
            }
            // MMA k-step: A frags via LDS.64 on permuted layout (R9-verified)
            const int c8 = sub * 8;
            uint32_t af[2][4];
            #pragma unroll
            for (int mt = 0; mt < 2; mt++) {
                float2 pa = *(const float2*)&wnc[(c8 + q)     * SA + (mblk + mt) * 16 + g * 2];
                float2 pb = *(const float2*)&wnc[(c8 + q + 4) * SA + (mblk + mt) * 16 + g * 2];
                af[mt][0] = __float_as_uint(pa.x);
                af[mt][1] = __float_as_uint(pa.y);
                af[mt][2] = __float_as_uint(pb.x);
                af[mt][3] = __float_as_uint(pb.y);
            }
            uint32_t bf[8][2];
            #pragma unroll
            for (int nt = 0; nt < 8; nt++) {
                const int bpx = n0 + nt * 8 + g;
                bf[nt][0] = __float_as_uint(colc[bpx * SB + c8 + q]);
                bf[nt][1] = __float_as_uint(colc[bpx * SB + c8 + q + 4]);
            }
            #pragma unroll
            for (int mt = 0; mt < 2; mt++)
                #pragma unroll
                for (int nt = 0; nt < 8; nt++)
                    mma_tf32(acc[mt][nt], af[mt], bf[nt]);
        }
        if (more) CP_WAIT0();
    }

    // ---- epilogue: out[b][cout][ho][wo] ----
    const int ho = ho0 + (n0 >> 6);
    #pragma unroll
    for (int mt = 0; mt < 2; mt++) {
        const int r0 = m0 + mt * 16 + g;
        #pragma unroll
        for (int nt = 0; nt < 8; nt++) {
            const int wo = nt * 8 + 2 * q;
            float2 v0 = make_float2(acc[mt][nt][0], acc[mt][nt][1]);
            float2 v1 = make_float2(acc[mt][nt][2], acc[mt][nt][3]);
            *(float2*)&out[((size_t)(b * 128 + r0)     * HW) + ho * Wn + wo] = v0;
            *(float2*)&out[((size_t)(b * 128 + r0 + 8) * HW) + ho * Wn + wo] = v1;
        }
    }
}

// ---------------------------------------------------------------------------
extern "C" void kernel_launch(void* const* d_in, const int* in_sizes, int n_in,
                              void* d_out, int out_size) {
    const float* x      = (const float*)d_in[0];   // (8,128,64,64)
    const float* offset = (const float*)d_in[1];   // (8,18,64,64)
    const float* weight = (const float*)d_in[2];   // (128,128,3,3)
    float* out = (float*)d_out;                    // (8,128,64,64)

    cudaFuncSetAttribute(deform_main_kernel,
                         cudaFuncAttributeMaxDynamicSharedMemorySize, SMEM_BYTES);
    prep_kernel<<<4096 + 36, 256>>>(x, weight);
    deform_main_kernel<<<256, 256, SMEM_BYTES>>>(offset, out);
}

// round 15
// speedup vs baseline: 1.6624x; 1.6624x over previous
#include <cuda_runtime.h>
#include <cstdint>

#define Bn 8
#define Hn 64
#define Wn 64
#define HW 4096
#define KK 9
#define EPSV 1e-4f
#define SA 136   // wn_s row stride (floats)
#define SB 36    // cols_s row stride (floats)

#define WN_FL   (32 * SA)
#define COL_FL  (128 * SB)
#define ST_FL   (128 * 8)
#define SMEM_BYTES ((2 * (WN_FL + COL_FL) + 2 * ST_FL) * 4)   // 79872 B

__device__ float g_xt[Bn * HW * 128];       // x transposed [b][hw][c]
__device__ float g_wnt[KK * 128 * 128];     // wn [k][c][o-permuted], tf32-rounded

__device__ __forceinline__ float to_tf32(float x) {
    float r; asm("cvt.rna.tf32.f32 %0, %1;" : "=f"(r) : "f"(x)); return r;
}
__device__ __forceinline__ uint32_t smem_u32(const void* p) {
    uint32_t a;
    asm("{ .reg .u64 t; cvta.to.shared.u64 t, %1; cvt.u32.u64 %0, t; }" : "=r"(a) : "l"(p));
    return a;
}
__device__ __forceinline__ void mma_tf32(float* d, const uint32_t* a, const uint32_t* b) {
    asm volatile(
        "mma.sync.aligned.m16n8k8.row.col.f32.tf32.tf32.f32 "
        "{%0,%1,%2,%3}, {%4,%5,%6,%7}, {%8,%9}, {%0,%1,%2,%3};"
        : "+f"(d[0]), "+f"(d[1]), "+f"(d[2]), "+f"(d[3])
        : "r"(a[0]), "r"(a[1]), "r"(a[2]), "r"(a[3]), "r"(b[0]), "r"(b[1]));
}
#define CP_ASYNC16(dst, src) \
    asm volatile("cp.async.ca.shared.global [%0], [%1], 16;" :: "r"(dst), "l"(src) : "memory")
#define CP_COMMIT()  asm volatile("cp.async.commit_group;" ::: "memory")
#define CP_WAIT0()   asm volatile("cp.async.wait_group 0;" ::: "memory")

// compute bilinear state for pixel px, tap k -> 8 floats {w00..w11, i00..i11}
__device__ __forceinline__ void write_state(float* stp, const float* __restrict__ offset,
                                            int b, int k, int px, int ho0) {
    const int gho = ho0 + (px >> 6), gwo = px & 63;
    const int ky = k / 3, kx = k - ky * 3;
    const float offy = __ldg(&offset[(((b * 18) + 2 * k    ) * Hn + gho) * Wn + gwo]);
    const float offx = __ldg(&offset[(((b * 18) + 2 * k + 1) * Hn + gho) * Wn + gwo]);
    const float py  = (float)(gho - 1 + ky) + offy;
    const float pxf = (float)(gwo - 1 + kx) + offx;
    const float y0f = floorf(py), x0f = floorf(pxf);
    const float ly = py - y0f, lx = pxf - x0f;
    const int y0 = (int)y0f, x0 = (int)x0f, y1 = y0 + 1, x1 = x0 + 1;
    float w00 = (1.f - ly) * (1.f - lx), w01 = (1.f - ly) * lx;
    float w10 = ly * (1.f - lx),        w11 = ly * lx;
    if (!((y0 >= 0) & (y0 < Hn) & (x0 >= 0) & (x0 < Wn))) w00 = 0.f;
    if (!((y0 >= 0) & (y0 < Hn) & (x1 >= 0) & (x1 < Wn))) w01 = 0.f;
    if (!((y1 >= 0) & (y1 < Hn) & (x0 >= 0) & (x0 < Wn))) w10 = 0.f;
    if (!((y1 >= 0) & (y1 < Hn) & (x1 >= 0) & (x1 < Wn))) w11 = 0.f;
    const int yc0 = min(max(y0, 0), Hn - 1), yc1 = min(max(y1, 0), Hn - 1);
    const int xc0 = min(max(x0, 0), Wn - 1), xc1 = min(max(x1, 0), Wn - 1);
    *(float4*)&stp[px * 8] = make_float4(w00, w01, w10, w11);
    *(float4*)&stp[px * 8 + 4] =
        make_float4(__int_as_float(yc0 * Wn + xc0), __int_as_float(yc0 * Wn + xc1),
                    __int_as_float(yc1 * Wn + xc0), __int_as_float(yc1 * Wn + xc1));
}

// ---- kernel 1: prep = transpose x (4096 blocks) + weights (36 blocks) ----
__global__ void prep_kernel(const float* __restrict__ x, const float* __restrict__ w) {
    if (blockIdx.x < 4096) {
        __shared__ float s[32][33];
        int id = blockIdx.x;
        int b = id >> 9, rest = id & 511;
        int c0 = (rest >> 7) * 32, hw0 = (rest & 127) * 32;
        int tx = threadIdx.x & 31, ty = threadIdx.x >> 5;
        #pragma unroll
        for (int p = 0; p < 4; p++)
            s[ty + p * 8][tx] = x[(size_t)(b * 128 + c0 + ty + p * 8) * HW + hw0 + tx];
        __syncthreads();
        #pragma unroll
        for (int p = 0; p < 4; p++)
            g_xt[(size_t)(b * HW + hw0 + ty + p * 8) * 128 + c0 + tx] = s[tx][ty + p * 8];
    } else {
        const int wb = blockIdx.x - 4096;
        const int k = wb >> 2, og = wb & 3;
        const int t = threadIdx.x;
        __shared__ float part[32][8];
        __shared__ float inv_s[32];
        {
            const int ol = t >> 3, sl = t & 7;
            const int o = og * 32 + ol;
            float s = 0.f;
            #pragma unroll
            for (int c = sl * 16; c < sl * 16 + 16; c++) {
                float v = w[(o * 128 + c) * KK + k]; s += v * v;
            }
            part[ol][sl] = s;
        }
        __syncthreads();
        if (t < 32) {
            float s = 0.f;
            #pragma unroll
            for (int j = 0; j < 8; j++) s += part[t][j];
            inv_s[t] = 1.0f / (sqrtf(s + 128.0f * EPSV) * 3.0f);
        }
        __syncthreads();
        #pragma unroll
        for (int r = 0; r < 16; r++) {
            int e = r * 256 + t;
            int c = e >> 5, ol = e & 31;
            int o = og * 32 + ol;
            // o-permutation: rows (g, g+8) of each 16-block adjacent -> LDS.64 A frags
            const int opos = (o >> 4) * 16 + (o & 7) * 2 + ((o >> 3) & 1);
            g_wnt[(k * 128 + c) * 128 + opos] =
                to_tf32(w[(o * 128 + c) * KK + k] * inv_s[ol]);
        }
    }
}

// ---- kernel 2: main — R13 pipeline + LDS.64 A fragments ----
// grid 256, 256 thr, 2 CTAs/SM. block = (b, 2 rows): D[128co][128px]
__global__ __launch_bounds__(256, 2)
void deform_main_kernel(const float* __restrict__ offset, float* __restrict__ out) {
    extern __shared__ float sm[];
    float* wnb[2]  = { sm, sm + WN_FL };
    float* colb[2] = { sm + 2 * WN_FL, sm + 2 * WN_FL + COL_FL };
    float* st      = sm + 2 * WN_FL + 2 * COL_FL;   // [2][128*8]
    const uint32_t wnb_u32[2] = { smem_u32(wnb[0]), smem_u32(wnb[1]) };

    const int t = threadIdx.x;
    const int b = blockIdx.x >> 5;
    const int ho0 = (blockIdx.x & 31) * 2;

    // gather mapping: 8 lanes/pixel, 4 passes of 32 px; lane covers 4 channels
    const int l8  = t & 7;
    const int pxq = t >> 3;
    // mma mapping: 8 warps = 4m x 2n
    const int w = t >> 5, lane = t & 31;
    const int m0 = (w & 3) * 32, n0 = (w >> 2) * 64;
    const int g = lane >> 2, q = lane & 3;
    const int mblk = (w & 3) * 2;           // base 16-block index of this warp

    float acc[2][8][4];
    #pragma unroll
    for (int mt = 0; mt < 2; mt++)
        #pragma unroll
        for (int nt = 0; nt < 8; nt++)
            #pragma unroll
            for (int r = 0; r < 4; r++) acc[mt][nt][r] = 0.f;

    const float* xb = g_xt + (size_t)b * HW * 128;

    // ---- prologue ----
    if (t < 128) write_state(st, offset, b, 0, t, ho0);   // k=0 -> slot 0
    {
        const float* src = g_wnt;   // wn chunk 0
        #pragma unroll
        for (int p = 0; p < 4; p++) {
            int e16 = p * 256 + t;
            int c = e16 >> 5, off = (e16 & 31) * 4;
            CP_ASYNC16(wnb_u32[0] + (uint32_t)(c * SA + off) * 4, src + e16 * 4);
        }
        CP_COMMIT();
    }
    __syncthreads();    // state(k0) visible
    #pragma unroll
    for (int p = 0; p < 4; p++) {    // gather chunk 0 into colb[0]
        const int px = p * 32 + pxq;
        float4 sw = *(const float4*)&st[px * 8];
        float4 si = *(const float4*)&st[px * 8 + 4];
        const float* base = xb + l8 * 4;
        float4 a  = *(const float4*)(base + (size_t)__float_as_int(si.x) * 128);
        float4 bb = *(const float4*)(base + (size_t)__float_as_int(si.y) * 128);
        float4 c  = *(const float4*)(base + (size_t)__float_as_int(si.z) * 128);
        float4 d  = *(const float4*)(base + (size_t)__float_as_int(si.w) * 128);
        float4 v;
        v.x = to_tf32(sw.x * a.x + sw.y * bb.x + sw.z * c.x + sw.w * d.x);
        v.y = to_tf32(sw.x * a.y + sw.y * bb.y + sw.z * c.y + sw.w * d.y);
        v.z = to_tf32(sw.x * a.z + sw.y * bb.z + sw.z * c.z + sw.w * d.z);
        v.w = to_tf32(sw.x * a.w + sw.y * bb.w + sw.z * c.w + sw.w * d.w);
        *(float4*)&colb[0][px * SB + l8 * 4] = v;
    }
    CP_WAIT0();

    // ---- pipelined main loop over 36 chunks ----
    for (int it = 0; it < 36; it++) {
        const int cur = it & 1, nxt = cur ^ 1;
        __syncthreads();

        const bool more = (it + 1 < 36);
        if (more) {
            const float* src = g_wnt + (size_t)(it + 1) * 4096;
            #pragma unroll
            for (int p = 0; p < 4; p++) {
                int e16 = p * 256 + t;
                int c = e16 >> 5, off = (e16 & 31) * 4;
                CP_ASYNC16(wnb_u32[nxt] + (uint32_t)(c * SA + off) * 4, src + e16 * 4);
            }
            CP_COMMIT();
        }
        // write state 2 chunks ahead (slot alternates with the one being read)
        if ((it + 2 < 36) && (((it + 2) & 3) == 0) && t < 128)
            write_state(st + (((it + 2) >> 2) & 1) * ST_FL, offset, b, (it + 2) >> 2, t, ho0);

        const float* stp = st + ((((it + 1) >> 2)) & 1) * ST_FL;
        const int ccn = (it + 1) & 3;
        const float* wnc = wnb[cur];
        const float* colc = colb[cur];
        float* coln = colb[nxt];

        #pragma unroll
        for (int sub = 0; sub < 4; sub++) {
            // issue next-chunk corner loads: pass `sub` (pixels sub*32..+31)
            float4 a, bb, c, d, swv;
            int px = 0;
            if (more) {
                px = sub * 32 + pxq;
                swv = *(const float4*)&stp[px * 8];
                float4 si = *(const float4*)&stp[px * 8 + 4];
                const float* base = xb + ccn * 32 + l8 * 4;
                a  = *(const float4*)(base + (size_t)__float_as_int(si.x) * 128);
                bb = *(const float4*)(base + (size_t)__float_as_int(si.y) * 128);
                c  = *(const float4*)(base + (size_t)__float_as_int(si.z) * 128);
                d  = *(const float4*)(base + (size_t)__float_as_int(si.w) * 128);
            }
            // MMA k-step: A frags as LDS.64 pairs on permuted layout
            const int c8 = sub * 8;
            uint32_t af[2][4];
            #pragma unroll
            for (int mt = 0; mt < 2; mt++) {
                float2 pa = *(const float2*)&wnc[(c8 + q)     * SA + (mblk + mt) * 16 + g * 2];
                float2 pb = *(const float2*)&wnc[(c8 + q + 4) * SA + (mblk + mt) * 16 + g * 2];
                af[mt][0] = __float_as_uint(pa.x);
                af[mt][1] = __float_as_uint(pa.y);
                af[mt][2] = __float_as_uint(pb.x);
                af[mt][3] = __float_as_uint(pb.y);
            }
            uint32_t bf[8][2];
            #pragma unroll
            for (int nt = 0; nt < 8; nt++) {
                const int bpx = n0 + nt * 8 + g;
                bf[nt][0] = __float_as_uint(colc[bpx * SB + c8 + q]);
                bf[nt][1] = __float_as_uint(colc[bpx * SB + c8 + q + 4]);
            }
            #pragma unroll
            for (int mt = 0; mt < 2; mt++)
                #pragma unroll
                for (int nt = 0; nt < 8; nt++)
                    mma_tf32(acc[mt][nt], af[mt], bf[nt]);

            // blend + STS.128 (one full 128B row per 8-lane pixel group)
            if (more) {
                float4 v;
                v.x = to_tf32(swv.x * a.x + swv.y * bb.x + swv.z * c.x + swv.w * d.x);
                v.y = to_tf32(swv.x * a.y + swv.y * bb.y + swv.z * c.y + swv.w * d.y);
                v.z = to_tf32(swv.x * a.z + swv.y * bb.z + swv.z * c.z + swv.w * d.z);
                v.w = to_tf32(swv.x * a.w + swv.y * bb.w + swv.z * c.w + swv.w * d.w);
                *(float4*)&coln[px * SB + l8 * 4] = v;
            }
        }
        if (more) CP_WAIT0();
    }

    // ---- epilogue: out[b][cout][ho][wo] (undo o-permutation: r0 rows are
    // the ORIGINAL cout indices; permutation only reordered smem columns,
    // and A-frag loads re-map them back so acc rows = original couts) ----
    const int ho = ho0 + (n0 >> 6);
    #pragma unroll
    for (int mt = 0; mt < 2; mt++) {
        const int r0 = m0 + mt * 16 + g;
        #pragma unroll
        for (int nt = 0; nt < 8; nt++) {
            const int wo = nt * 8 + 2 * q;
            float2 v0 = make_float2(acc[mt][nt][0], acc[mt][nt][1]);
            float2 v1 = make_float2(acc[mt][nt][2], acc[mt][nt][3]);
            *(float2*)&out[((size_t)(b * 128 + r0)     * HW) + ho * Wn + wo] = v0;
            *(float2*)&out[((size_t)(b * 128 + r0 + 8) * HW) + ho * Wn + wo] = v1;
        }
    }
}

// ---------------------------------------------------------------------------
extern "C" void kernel_launch(void* const* d_in, const int* in_sizes, int n_in,
                              void* d_out, int out_size) {
    const float* x      = (const float*)d_in[0];   // (8,128,64,64)
    const float* offset = (const float*)d_in[1];   // (8,18,64,64)
    const float* weight = (const float*)d_in[2];   // (128,128,3,3)
    float* out = (float*)d_out;                    // (8,128,64,64)

    cudaFuncSetAttribute(deform_main_kernel,
                         cudaFuncAttributeMaxDynamicSharedMemorySize, SMEM_BYTES);
    prep_kernel<<<4096 + 36, 256>>>(x, weight);
    deform_main_kernel<<<256, 256, SMEM_BYTES>>>(offset, out);
}

// round 16
// speedup vs baseline: 2.0570x; 1.2373x over previous
#include <cuda_runtime.h>
#include <cuda_fp16.h>
#include <cstdint>

#define Bn 8
#define Hn 64
#define Wn 64
#define HW 4096
#define KK 9
#define EPSV 1e-4f
#define SAH 40   // wn_s row stride (halves): g*20+q distinct mod 32 -> conflict-free
#define SBH 40   // cols_s row stride (halves)

#define WN_H    (128 * SAH)                 // 5120 halves per wn stage
#define COL_H   (128 * SBH)                 // 5120 halves per cols stage
#define ST_FL   (128 * 8)                   // 1024 floats per state slot
#define SMEM_BYTES (2 * (WN_H + COL_H) * 2 + 2 * ST_FL * 4)   // 49152 B

__device__ float  g_xt[Bn * HW * 128];      // x transposed [b][hw][c], fp32
__device__ __half g_wnth[KK * 128 * 128];   // wn [k][o][c], fp16

__device__ __forceinline__ uint32_t smem_u32(const void* p) {
    uint32_t a;
    asm("{ .reg .u64 t; cvta.to.shared.u64 t, %1; cvt.u32.u64 %0, t; }" : "=r"(a) : "l"(p));
    return a;
}
__device__ __forceinline__ void mma_f16(float* d, const uint32_t* a, const uint32_t* b) {
    asm volatile(
        "mma.sync.aligned.m16n8k16.row.col.f32.f16.f16.f32 "
        "{%0,%1,%2,%3}, {%4,%5,%6,%7}, {%8,%9}, {%0,%1,%2,%3};"
        : "+f"(d[0]), "+f"(d[1]), "+f"(d[2]), "+f"(d[3])
        : "r"(a[0]), "r"(a[1]), "r"(a[2]), "r"(a[3]), "r"(b[0]), "r"(b[1]));
}
#define CP_ASYNC16(dst, src) \
    asm volatile("cp.async.ca.shared.global [%0], [%1], 16;" :: "r"(dst), "l"(src) : "memory")
#define CP_COMMIT()  asm volatile("cp.async.commit_group;" ::: "memory")
#define CP_WAIT0()   asm volatile("cp.async.wait_group 0;" ::: "memory")

// bilinear state for pixel px, tap k -> {w00..w11, i00..i11}
__device__ __forceinline__ void write_state(float* stp, const float* __restrict__ offset,
                                            int b, int k, int px, int ho0) {
    const int gho = ho0 + (px >> 6), gwo = px & 63;
    const int ky = k / 3, kx = k - ky * 3;
    const float offy = __ldg(&offset[(((b * 18) + 2 * k    ) * Hn + gho) * Wn + gwo]);
    const float offx = __ldg(&offset[(((b * 18) + 2 * k + 1) * Hn + gho) * Wn + gwo]);
    const float py  = (float)(gho - 1 + ky) + offy;
    const float pxf = (float)(gwo - 1 + kx) + offx;
    const float y0f = floorf(py), x0f = floorf(pxf);
    const float ly = py - y0f, lx = pxf - x0f;
    const int y0 = (int)y0f, x0 = (int)x0f, y1 = y0 + 1, x1 = x0 + 1;
    float w00 = (1.f - ly) * (1.f - lx), w01 = (1.f - ly) * lx;
    float w10 = ly * (1.f - lx),        w11 = ly * lx;
    if (!((y0 >= 0) & (y0 < Hn) & (x0 >= 0) & (x0 < Wn))) w00 = 0.f;
    if (!((y0 >= 0) & (y0 < Hn) & (x1 >= 0) & (x1 < Wn))) w01 = 0.f;
    if (!((y1 >= 0) & (y1 < Hn) & (x0 >= 0) & (x0 < Wn))) w10 = 0.f;
    if (!((y1 >= 0) & (y1 < Hn) & (x1 >= 0) & (x1 < Wn))) w11 = 0.f;
    const int yc0 = min(max(y0, 0), Hn - 1), yc1 = min(max(y1, 0), Hn - 1);
    const int xc0 = min(max(x0, 0), Wn - 1), xc1 = min(max(x1, 0), Wn - 1);
    *(float4*)&stp[px * 8] = make_float4(w00, w01, w10, w11);
    *(float4*)&stp[px * 8 + 4] =
        make_float4(__int_as_float(yc0 * Wn + xc0), __int_as_float(yc0 * Wn + xc1),
                    __int_as_float(yc1 * Wn + xc0), __int_as_float(yc1 * Wn + xc1));
}

// ---- kernel 1: prep = transpose x (4096 blocks) + weights (36 blocks) ----
__global__ void prep_kernel(const float* __restrict__ x, const float* __restrict__ w) {
    if (blockIdx.x < 4096) {
        __shared__ float s[32][33];
        int id = blockIdx.x;
        int b = id >> 9, rest = id & 511;
        int c0 = (rest >> 7) * 32, hw0 = (rest & 127) * 32;
        int tx = threadIdx.x & 31, ty = threadIdx.x >> 5;
        #pragma unroll
        for (int p = 0; p < 4; p++)
            s[ty + p * 8][tx] = x[(size_t)(b * 128 + c0 + ty + p * 8) * HW + hw0 + tx];
        __syncthreads();
        #pragma unroll
        for (int p = 0; p < 4; p++)
            g_xt[(size_t)(b * HW + hw0 + ty + p * 8) * 128 + c0 + tx] = s[tx][ty + p * 8];
    } else {
        const int wb = blockIdx.x - 4096;
        const int k = wb >> 2, og = wb & 3;
        const int t = threadIdx.x;
        __shared__ float part[32][8];
        __shared__ float inv_s[32];
        {
            const int ol = t >> 3, sl = t & 7;
            const int o = og * 32 + ol;
            float s = 0.f;
            #pragma unroll
            for (int c = sl * 16; c < sl * 16 + 16; c++) {
                float v = w[(o * 128 + c) * KK + k]; s += v * v;
            }
            part[ol][sl] = s;
        }
        __syncthreads();
        if (t < 32) {
            float s = 0.f;
            #pragma unroll
            for (int j = 0; j < 8; j++) s += part[t][j];
            inv_s[t] = 1.0f / (sqrtf(s + 128.0f * EPSV) * 3.0f);
        }
        __syncthreads();
        // write [k][o][c], thread -> c (coalesced 2B x 128 = 256B rows)
        #pragma unroll
        for (int r = 0; r < 16; r++) {
            int e = r * 256 + t;
            int ol = e >> 7, c = e & 127;
            int o = og * 32 + ol;
            g_wnth[(size_t)(k * 128 + o) * 128 + c] =
                __float2half_rn(w[(o * 128 + c) * KK + k] * inv_s[ol]);
        }
    }
}

// ---- kernel 2: main — R13 gather pipeline + fp16 m16n8k16 GEMM ----
// grid 256, 256 thr, 2 CTAs/SM. block = (b, 2 rows): D[128co][128px]
__global__ __launch_bounds__(256, 2)
void deform_main_kernel(const float* __restrict__ offset, float* __restrict__ out) {
    extern __shared__ char smraw[];
    __half* wnb[2]  = { (__half*)smraw, (__half*)smraw + WN_H };
    __half* colb[2] = { (__half*)smraw + 2 * WN_H, (__half*)smraw + 2 * WN_H + COL_H };
    float*  st      = (float*)(smraw + (2 * (WN_H + COL_H)) * 2);   // [2][128*8]
    const uint32_t wnb_u32[2] = { smem_u32(wnb[0]), smem_u32(wnb[1]) };

    const int t = threadIdx.x;
    const int b = blockIdx.x >> 5;
    const int ho0 = (blockIdx.x & 31) * 2;

    // gather mapping: 8 lanes/pixel, 4 passes of 32 px; lane covers 4 channels
    const int l8  = t & 7;
    const int pxq = t >> 3;
    // mma mapping: 8 warps = 4m x 2n
    const int w = t >> 5, lane = t & 31;
    const int m0 = (w & 3) * 32, n0 = (w >> 2) * 64;
    const int g = lane >> 2, q = lane & 3;

    float acc[2][8][4];
    #pragma unroll
    for (int mt = 0; mt < 2; mt++)
        #pragma unroll
        for (int nt = 0; nt < 8; nt++)
            #pragma unroll
            for (int r = 0; r < 4; r++) acc[mt][nt][r] = 0.f;

    const float* xb = g_xt + (size_t)b * HW * 128;

    // ---- prologue ----
    if (t < 128) write_state(st, offset, b, 0, t, ho0);   // k=0 -> slot 0
    {
        // wn chunk 0: rows o=0..127, halves 0..31 (64B/row = 4 granules)
        #pragma unroll
        for (int p = 0; p < 2; p++) {
            int e = p * 256 + t;
            int row = e >> 2, off = e & 3;
            CP_ASYNC16(wnb_u32[0] + (uint32_t)(row * SAH + off * 8) * 2,
                       g_wnth + (size_t)row * 128 + off * 8);
        }
        CP_COMMIT();
    }
    __syncthreads();    // state(k0) visible
    #pragma unroll
    for (int p = 0; p < 4; p++) {    // gather chunk 0 into colb[0]
        const int px = p * 32 + pxq;
        float4 sw = *(const float4*)&st[px * 8];
        float4 si = *(const float4*)&st[px * 8 + 4];
        const float* base = xb + l8 * 4;
        float4 a  = *(const float4*)(base + (size_t)__float_as_int(si.x) * 128);
        float4 bb = *(const float4*)(base + (size_t)__float_as_int(si.y) * 128);
        float4 c  = *(const float4*)(base + (size_t)__float_as_int(si.z) * 128);
        float4 d  = *(const float4*)(base + (size_t)__float_as_int(si.w) * 128);
        __half2 h0 = __floats2half2_rn(sw.x * a.x + sw.y * bb.x + sw.z * c.x + sw.w * d.x,
                                       sw.x * a.y + sw.y * bb.y + sw.z * c.y + sw.w * d.y);
        __half2 h1 = __floats2half2_rn(sw.x * a.z + sw.y * bb.z + sw.z * c.z + sw.w * d.z,
                                       sw.x * a.w + sw.y * bb.w + sw.z * c.w + sw.w * d.w);
        *(uint2*)&colb[0][px * SBH + l8 * 4] = make_uint2(*(uint32_t*)&h0, *(uint32_t*)&h1);
    }
    CP_WAIT0();

    // ---- pipelined main loop over 36 chunks ----
    for (int it = 0; it < 36; it++) {
        const int cur = it & 1, nxt = cur ^ 1;
        __syncthreads();

        const bool more = (it + 1 < 36);
        if (more) {
            const int itn = it + 1;
            const __half* srcb = g_wnth + (size_t)(itn >> 2) * 128 * 128 + (itn & 3) * 32;
            #pragma unroll
            for (int p = 0; p < 2; p++) {
                int e = p * 256 + t;
                int row = e >> 2, off = e & 3;
                CP_ASYNC16(wnb_u32[nxt] + (uint32_t)(row * SAH + off * 8) * 2,
                           srcb + (size_t)row * 128 + off * 8);
            }
            CP_COMMIT();
        }
        if ((it + 2 < 36) && (((it + 2) & 3) == 0) && t < 128)
            write_state(st + (((it + 2) >> 2) & 1) * ST_FL, offset, b, (it + 2) >> 2, t, ho0);

        const float* stp = st + ((((it + 1) >> 2)) & 1) * ST_FL;
        const int ccn = (it + 1) & 3;
        const __half* wnc = wnb[cur];
        const __half* colc = colb[cur];
        __half* coln = colb[nxt];

        uint32_t bf[8][2];
        #pragma unroll
        for (int sub = 0; sub < 4; sub++) {
            const int ks = sub >> 1, mth = sub & 1;
            // issue next-chunk corner loads: pass `sub` (pixels sub*32..+31)
            float4 a, bb, c, d, swv;
            int px = 0;
            if (more) {
                px = sub * 32 + pxq;
                swv = *(const float4*)&stp[px * 8];
                float4 si = *(const float4*)&stp[px * 8 + 4];
                const float* base = xb + ccn * 32 + l8 * 4;
                a  = *(const float4*)(base + (size_t)__float_as_int(si.x) * 128);
                bb = *(const float4*)(base + (size_t)__float_as_int(si.y) * 128);
                c  = *(const float4*)(base + (size_t)__float_as_int(si.z) * 128);
                d  = *(const float4*)(base + (size_t)__float_as_int(si.w) * 128);
            }
            // MMA: kstep ks (k base ks*16), m-half mth (R10-verified mappings)
            const int cb = ks * 16;
            if (mth == 0) {
                #pragma unroll
                for (int nt = 0; nt < 8; nt++) {
                    const int bpx = n0 + nt * 8 + g;
                    bf[nt][0] = *(const uint32_t*)&colc[bpx * SBH + cb + 2 * q];
                    bf[nt][1] = *(const uint32_t*)&colc[bpx * SBH + cb + 2 * q + 8];
                }
            }
            uint32_t af[4];
            {
                const int row = m0 + mth * 16 + g;
                af[0] = *(const uint32_t*)&wnc[(row    ) * SAH + cb + 2 * q];
                af[1] = *(const uint32_t*)&wnc[(row + 8) * SAH + cb + 2 * q];
                af[2] = *(const uint32_t*)&wnc[(row    ) * SAH + cb + 2 * q + 8];
                af[3] = *(const uint32_t*)&wnc[(row + 8) * SAH + cb + 2 * q + 8];
            }
            #pragma unroll
            for (int nt = 0; nt < 8; nt++)
                mma_f16(acc[mth][nt], af, bf[nt]);

            // blend + cvt + STS.64 of this pass's gather
            if (more) {
                __half2 h0 = __floats2half2_rn(
                    swv.x * a.x + swv.y * bb.x + swv.z * c.x + swv.w * d.x,
                    swv.x * a.y + swv.y * bb.y + swv.z * c.y + swv.w * d.y);
                __half2 h1 = __floats2half2_rn(
                    swv.x * a.z + swv.y * bb.z + swv.z * c.z + swv.w * d.z,
                    swv.x * a.w + swv.y * bb.w + swv.z * c.w + swv.w * d.w);
                *(uint2*)&coln[px * SBH + l8 * 4] =
                    make_uint2(*(uint32_t*)&h0, *(uint32_t*)&h1);
            }
        }
        if (more) CP_WAIT0();
    }

    // ---- epilogue: out[b][cout][ho][wo] ----
    const int ho = ho0 + (n0 >> 6);
    #pragma unroll
    for (int mt = 0; mt < 2; mt++) {
        const int r0 = m0 + mt * 16 + g;
        #pragma unroll
        for (int nt = 0; nt < 8; nt++) {
            const int wo = nt * 8 + 2 * q;
            float2 v0 = make_float2(acc[mt][nt][0], acc[mt][nt][1]);
            float2 v1 = make_float2(acc[mt][nt][2], acc[mt][nt][3]);
            *(float2*)&out[((size_t)(b * 128 + r0)     * HW) + ho * Wn + wo] = v0;
            *(float2*)&out[((size_t)(b * 128 + r0 + 8) * HW) + ho * Wn + wo] = v1;
        }
    }
}

// ---------------------------------------------------------------------------
extern "C" void kernel_launch(void* const* d_in, const int* in_sizes, int n_in,
                              void* d_out, int out_size) {
    const float* x      = (const float*)d_in[0];   // (8,128,64,64)
    const float* offset = (const float*)d_in[1];   // (8,18,64,64)
    const float* weight = (const float*)d_in[2];   // (128,128,3,3)
    float* out = (float*)d_out;                    // (8,128,64,64)

    cudaFuncSetAttribute(deform_main_kernel,
                         cudaFuncAttributeMaxDynamicSharedMemorySize, SMEM_BYTES);
    prep_kernel<<<4096 + 36, 256>>>(x, weight);
    deform_main_kernel<<<256, 256, SMEM_BYTES>>>(offset, out);
}

// round 17
// speedup vs baseline: 2.6248x; 1.2760x over previous
#include <cuda_runtime.h>
#include <cuda_fp16.h>
#include <cstdint>

#define Bn 8
#define Hn 64
#define Wn 64
#define HW 4096
#define KK 9
#define EPSV 1e-4f
#define SAH 72   // wn_s row stride (halves): word (row*36+q) distinct mod 32
#define SBH 72   // cols_s row stride (halves)

#define WN_H    (128 * SAH)                 // 9216 halves per wn stage
#define COL_H   (128 * SBH)                 // 9216 halves per cols stage
#define ST_FL   (128 * 8)                   // 1024 floats per state slot
#define SMEM_BYTES (2 * (WN_H + COL_H) * 2 + 2 * ST_FL * 4)   // 81920 B

__device__ __half g_xth[Bn * HW * 128];     // x transposed [b][hw][c], fp16
__device__ __half g_wnth[KK * 128 * 128];   // wn [k][o][c], fp16

__device__ __forceinline__ uint32_t smem_u32(const void* p) {
    uint32_t a;
    asm("{ .reg .u64 t; cvta.to.shared.u64 t, %1; cvt.u32.u64 %0, t; }" : "=r"(a) : "l"(p));
    return a;
}
__device__ __forceinline__ void mma_f16(float* d, const uint32_t* a, const uint32_t* b) {
    asm volatile(
        "mma.sync.aligned.m16n8k16.row.col.f32.f16.f16.f32 "
        "{%0,%1,%2,%3}, {%4,%5,%6,%7}, {%8,%9}, {%0,%1,%2,%3};"
        : "+f"(d[0]), "+f"(d[1]), "+f"(d[2]), "+f"(d[3])
        : "r"(a[0]), "r"(a[1]), "r"(a[2]), "r"(a[3]), "r"(b[0]), "r"(b[1]));
}
#define CP_ASYNC16(dst, src) \
    asm volatile("cp.async.ca.shared.global [%0], [%1], 16;" :: "r"(dst), "l"(src) : "memory")
#define CP_COMMIT()  asm volatile("cp.async.commit_group;" ::: "memory")
#define CP_WAIT0()   asm volatile("cp.async.wait_group 0;" ::: "memory")

// bilinear state for pixel px, tap k -> {w00..w11, i00..i11}
__device__ __forceinline__ void write_state(float* stp, const float* __restrict__ offset,
                                            int b, int k, int px, int ho0) {
    const int gho = ho0 + (px >> 6), gwo = px & 63;
    const int ky = k / 3, kx = k - ky * 3;
    const float offy = __ldg(&offset[(((b * 18) + 2 * k    ) * Hn + gho) * Wn + gwo]);
    const float offx = __ldg(&offset[(((b * 18) + 2 * k + 1) * Hn + gho) * Wn + gwo]);
    const float py  = (float)(gho - 1 + ky) + offy;
    const float pxf = (float)(gwo - 1 + kx) + offx;
    const float y0f = floorf(py), x0f = floorf(pxf);
    const float ly = py - y0f, lx = pxf - x0f;
    const int y0 = (int)y0f, x0 = (int)x0f, y1 = y0 + 1, x1 = x0 + 1;
    float w00 = (1.f - ly) * (1.f - lx), w01 = (1.f - ly) * lx;
    float w10 = ly * (1.f - lx),        w11 = ly * lx;
    if (!((y0 >= 0) & (y0 < Hn) & (x0 >= 0) & (x0 < Wn))) w00 = 0.f;
    if (!((y0 >= 0) & (y0 < Hn) & (x1 >= 0) & (x1 < Wn))) w01 = 0.f;
    if (!((y1 >= 0) & (y1 < Hn) & (x0 >= 0) & (x0 < Wn))) w10 = 0.f;
    if (!((y1 >= 0) & (y1 < Hn) & (x1 >= 0) & (x1 < Wn))) w11 = 0.f;
    const int yc0 = min(max(y0, 0), Hn - 1), yc1 = min(max(y1, 0), Hn - 1);
    const int xc0 = min(max(x0, 0), Wn - 1), xc1 = min(max(x1, 0), Wn - 1);
    *(float4*)&stp[px * 8] = make_float4(w00, w01, w10, w11);
    *(float4*)&stp[px * 8 + 4] =
        make_float4(__int_as_float(yc0 * Wn + xc0), __int_as_float(yc0 * Wn + xc1),
                    __int_as_float(yc1 * Wn + xc0), __int_as_float(yc1 * Wn + xc1));
}

// ---- kernel 1: prep = transpose x to fp16 (4096 blocks) + weights (36) ----
__global__ void prep_kernel(const float* __restrict__ x, const float* __restrict__ w) {
    if (blockIdx.x < 4096) {
        __shared__ float s[32][33];
        int id = blockIdx.x;
        int b = id >> 9, rest = id & 511;
        int c0 = (rest >> 7) * 32, hw0 = (rest & 127) * 32;
        int tx = threadIdx.x & 31, ty = threadIdx.x >> 5;
        #pragma unroll
        for (int p = 0; p < 4; p++)
            s[ty + p * 8][tx] = x[(size_t)(b * 128 + c0 + ty + p * 8) * HW + hw0 + tx];
        __syncthreads();
        #pragma unroll
        for (int p = 0; p < 4; p++)
            g_xth[(size_t)(b * HW + hw0 + ty + p * 8) * 128 + c0 + tx] =
                __float2half_rn(s[tx][ty + p * 8]);
    } else {
        const int wb = blockIdx.x - 4096;
        const int k = wb >> 2, og = wb & 3;
        const int t = threadIdx.x;
        __shared__ float part[32][8];
        __shared__ float inv_s[32];
        {
            const int ol = t >> 3, sl = t & 7;
            const int o = og * 32 + ol;
            float s = 0.f;
            #pragma unroll
            for (int c = sl * 16; c < sl * 16 + 16; c++) {
                float v = w[(o * 128 + c) * KK + k]; s += v * v;
            }
            part[ol][sl] = s;
        }
        __syncthreads();
        if (t < 32) {
            float s = 0.f;
            #pragma unroll
            for (int j = 0; j < 8; j++) s += part[t][j];
            inv_s[t] = 1.0f / (sqrtf(s + 128.0f * EPSV) * 3.0f);
        }
        __syncthreads();
        #pragma unroll
        for (int r = 0; r < 16; r++) {
            int e = r * 256 + t;
            int ol = e >> 7, c = e & 127;
            int o = og * 32 + ol;
            g_wnth[(size_t)(k * 128 + o) * 128 + c] =
                __float2half_rn(w[(o * 128 + c) * KK + k] * inv_s[ol]);
        }
    }
}

// ---- kernel 2: main — fp16 gather (64-ch chunks) + fp16 m16n8k16 GEMM ----
// grid 256, 256 thr, 2 CTAs/SM. block = (b, 2 rows): D[128co][128px], 18 chunks
__global__ __launch_bounds__(256, 2)
void deform_main_kernel(const float* __restrict__ offset, float* __restrict__ out) {
    extern __shared__ char smraw[];
    __half* wnb[2]  = { (__half*)smraw, (__half*)smraw + WN_H };
    __half* colb[2] = { (__half*)smraw + 2 * WN_H, (__half*)smraw + 2 * WN_H + COL_H };
    float*  st      = (float*)(smraw + (2 * (WN_H + COL_H)) * 2);   // [2][128*8]
    const uint32_t wnb_u32[2] = { smem_u32(wnb[0]), smem_u32(wnb[1]) };

    const int t = threadIdx.x;
    const int b = blockIdx.x >> 5;
    const int ho0 = (blockIdx.x & 31) * 2;

    // gather mapping: 8 lanes/pixel, 4 passes of 32 px; lane covers 8 fp16 ch
    const int l8  = t & 7;
    const int pxq = t >> 3;
    // mma mapping: 8 warps = 4m x 2n
    const int w = t >> 5, lane = t & 31;
    const int m0 = (w & 3) * 32, n0 = (w >> 2) * 64;
    const int g = lane >> 2, q = lane & 3;

    float acc[2][8][4];
    #pragma unroll
    for (int mt = 0; mt < 2; mt++)
        #pragma unroll
        for (int nt = 0; nt < 8; nt++)
            #pragma unroll
            for (int r = 0; r < 4; r++) acc[mt][nt][r] = 0.f;

    const __half* xb = g_xth + (size_t)b * HW * 128;

    // ---- prologue ----
    if (t < 128) write_state(st, offset, b, 0, t, ho0);   // k=0 -> slot 0
    {
        // wn chunk 0 (k=0, first 64 ch): 128 rows x 128B = 4 granules/thread
        #pragma unroll
        for (int p = 0; p < 4; p++) {
            int e = p * 256 + t;
            int row = e >> 3, off = e & 7;
            CP_ASYNC16(wnb_u32[0] + (uint32_t)(row * SAH + off * 8) * 2,
                       g_wnth + (size_t)row * 128 + off * 8);
        }
        CP_COMMIT();
    }
    __syncthreads();    // state(k0) visible
    #pragma unroll
    for (int p = 0; p < 4; p++) {    // gather chunk 0 (64 ch) into colb[0]
        const int px = p * 32 + pxq;
        float4 sw = *(const float4*)&st[px * 8];
        float4 si = *(const float4*)&st[px * 8 + 4];
        const __half* base = xb + l8 * 8;
        uint4 ua = *(const uint4*)(base + (size_t)__float_as_int(si.x) * 128);
        uint4 ub = *(const uint4*)(base + (size_t)__float_as_int(si.y) * 128);
        uint4 uc = *(const uint4*)(base + (size_t)__float_as_int(si.z) * 128);
        uint4 ud = *(const uint4*)(base + (size_t)__float_as_int(si.w) * 128);
        uint4 uv;
        #pragma unroll
        for (int i = 0; i < 4; i++) {
            float2 fa = __half22float2(((const __half2*)&ua)[i]);
            float2 fb = __half22float2(((const __half2*)&ub)[i]);
            float2 fc = __half22float2(((const __half2*)&uc)[i]);
            float2 fd = __half22float2(((const __half2*)&ud)[i]);
            __half2 hv = __floats2half2_rn(
                sw.x * fa.x + sw.y * fb.x + sw.z * fc.x + sw.w * fd.x,
                sw.x * fa.y + sw.y * fb.y + sw.z * fc.y + sw.w * fd.y);
            ((uint32_t*)&uv)[i] = *(uint32_t*)&hv;
        }
        *(uint4*)&colb[0][px * SBH + l8 * 8] = uv;
    }
    CP_WAIT0();

    // ---- pipelined main loop over 18 chunks of K=64 ----
    for (int it = 0; it < 18; it++) {
        const int cur = it & 1, nxt = cur ^ 1;
        __syncthreads();

        const bool more = (it + 1 < 18);
        if (more) {
            const int itn = it + 1;
            const __half* srcb = g_wnth + (size_t)(itn >> 1) * 16384 + (itn & 1) * 64;
            #pragma unroll
            for (int p = 0; p < 4; p++) {
                int e = p * 256 + t;
                int row = e >> 3, off = e & 7;
                CP_ASYNC16(wnb_u32[nxt] + (uint32_t)(row * SAH + off * 8) * 2,
                           srcb + (size_t)row * 128 + off * 8);
            }
            CP_COMMIT();
        }
        // state for k=(it+2)/2 written one chunk-pair ahead (slot = k parity)
        if ((it + 2 < 18) && !((it + 2) & 1) && t < 128)
            write_state(st + (((it + 2) >> 1) & 1) * ST_FL, offset, b, (it + 2) >> 1, t, ho0);

        const float* stp = st + ((((it + 1) >> 1)) & 1) * ST_FL;
        const int ccn = (it + 1) & 1;           // 64-ch half of tap k for next chunk
        const __half* wnc = wnb[cur];
        const __half* colc = colb[cur];
        __half* coln = colb[nxt];

        uint32_t bf[8][2];
        uint4 ua, ub, uc, ud; float4 swv; int gpx = 0;
        #pragma unroll
        for (int sub = 0; sub < 8; sub++) {
            const int ks = sub >> 1, mth = sub & 1;
            // even sub: issue corner loads for pass ks (pixels ks*32..+31)
            if (more && mth == 0) {
                gpx = ks * 32 + pxq;
                swv = *(const float4*)&stp[gpx * 8];
                float4 si = *(const float4*)&stp[gpx * 8 + 4];
                const __half* base = xb + ccn * 64 + l8 * 8;
                ua = *(const uint4*)(base + (size_t)__float_as_int(si.x) * 128);
                ub = *(const uint4*)(base + (size_t)__float_as_int(si.y) * 128);
                uc = *(const uint4*)(base + (size_t)__float_as_int(si.z) * 128);
                ud = *(const uint4*)(base + (size_t)__float_as_int(si.w) * 128);
            }
            // MMA: kstep ks (k base ks*16 halves), m-half mth
            const int cb = ks * 16;
            if (mth == 0) {
                #pragma unroll
                for (int nt = 0; nt < 8; nt++) {
                    const int bpx = n0 + nt * 8 + g;
                    bf[nt][0] = *(const uint32_t*)&colc[bpx * SBH + cb + 2 * q];
                    bf[nt][1] = *(const uint32_t*)&colc[bpx * SBH + cb + 2 * q + 8];
                }
            }
            uint32_t af[4];
            {
                const int row = m0 + mth * 16 + g;
                af[0] = *(const uint32_t*)&wnc[(row    ) * SAH + cb + 2 * q];
                af[1] = *(const uint32_t*)&wnc[(row + 8) * SAH + cb + 2 * q];
                af[2] = *(const uint32_t*)&wnc[(row    ) * SAH + cb + 2 * q + 8];
                af[3] = *(const uint32_t*)&wnc[(row + 8) * SAH + cb + 2 * q + 8];
            }
            #pragma unroll
            for (int nt = 0; nt < 8; nt++)
                mma_f16(acc[mth][nt], af, bf[nt]);

            // odd sub: blend + store pass ks's corners (issued one sub ago)
            if (more && mth == 1) {
                uint4 uv;
                #pragma unroll
                for (int i = 0; i < 4; i++) {
                    float2 fa = __half22float2(((const __half2*)&ua)[i]);
                    float2 fb = __half22float2(((const __half2*)&ub)[i]);
                    float2 fc = __half22float2(((const __half2*)&uc)[i]);
                    float2 fd = __half22float2(((const __half2*)&ud)[i]);
                    __half2 hv = __floats2half2_rn(
                        swv.x * fa.x + swv.y * fb.x + swv.z * fc.x + swv.w * fd.x,
                        swv.x * fa.y + swv.y * fb.y + swv.z * fc.y + swv.w * fd.y);
                    ((uint32_t*)&uv)[i] = *(uint32_t*)&hv;
                }
                *(uint4*)&coln[gpx * SBH + l8 * 8] = uv;
            }
        }
        if (more) CP_WAIT0();
    }

    // ---- epilogue: out[b][cout][ho][wo] ----
    const int ho = ho0 + (n0 >> 6);
    #pragma unroll
    for (int mt = 0; mt < 2; mt++) {
        const int r0 = m0 + mt * 16 + g;
        #pragma unroll
        for (int nt = 0; nt < 8; nt++) {
            const int wo = nt * 8 + 2 * q;
            float2 v0 = make_float2(acc[mt][nt][0], acc[mt][nt][1]);
            float2 v1 = make_float2(acc[mt][nt][2], acc[mt][nt][3]);
            *(float2*)&out[((size_t)(b * 128 + r0)     * HW) + ho * Wn + wo] = v0;
            *(float2*)&out[((size_t)(b * 128 + r0 + 8) * HW) + ho * Wn + wo] = v1;
        }
    }
}

// ---------------------------------------------------------------------------
extern "C" void kernel_launch(void* const* d_in, const int* in_sizes, int n_in,
                              void* d_out, int out_size) {
    const float* x      = (const float*)d_in[0];   // (8,128,64,64)
    const float* offset = (const float*)d_in[1];   // (8,18,64,64)
    const float* weight = (const float*)d_in[2];   // (128,128,3,3)
    float* out = (float*)d_out;                    // (8,128,64,64)

    cudaFuncSetAttribute(deform_main_kernel,
                         cudaFuncAttributeMaxDynamicSharedMemorySize, SMEM_BYTES);
    prep_kernel<<<4096 + 36, 256>>>(x, weight);
    deform_main_kernel<<<256, 256, SMEM_BYTES>>>(offset, out);
}